// round 1
// baseline (speedup 1.0000x reference)
#include <cuda_runtime.h>
#include <math.h>
#include <stdint.h>

// Problem constants
#define MCOLS 65536          // spatial columns (16*64*64)
#define TCH   64             // channels / NMF rows
#define LRANK 8              // NMF rank
#define NMF_ITERS 50
#define EPS_F 1.1920929e-07f

// ---------------------------------------------------------------------------
// Scratch (static __device__ — no allocations allowed)
// ---------------------------------------------------------------------------
__device__ __align__(16) float g_V[TCH * MCOLS];      // 16.7 MB, relu(conv) result
__device__ __align__(16) float g_H[LRANK * MCOLS];    // 2 MB
__device__ __align__(16) float g_W[TCH * LRANK];
__device__ __align__(16) float g_A[TCH * LRANK];      // w_post1 @ W
__device__ __align__(16) float g_partial[576 * 128];  // [idx][block] transposed partials
__device__ float g_red[256];
__device__ float g_red2[256];
__device__ float g_avg;
__device__ unsigned g_keys[4];                        // kW (2), kH (2)

// ---------------------------------------------------------------------------
// Threefry-2x32 (Random123 / JAX), 20 rounds
// ---------------------------------------------------------------------------
__device__ __forceinline__ void tf2x32(unsigned k0, unsigned k1,
                                       unsigned x0, unsigned x1,
                                       unsigned& o0, unsigned& o1) {
    unsigned ks2 = k0 ^ k1 ^ 0x1BD11BDAu;
    x0 += k0; x1 += k1;
#define TF_RND(r) { x0 += x1; x1 = (x1 << (r)) | (x1 >> (32 - (r))); x1 ^= x0; }
    TF_RND(13) TF_RND(15) TF_RND(26) TF_RND(6)
    x0 += k1;  x1 += ks2 + 1u;
    TF_RND(17) TF_RND(29) TF_RND(16) TF_RND(24)
    x0 += ks2; x1 += k0 + 2u;
    TF_RND(13) TF_RND(15) TF_RND(26) TF_RND(6)
    x0 += k0;  x1 += k1 + 3u;
    TF_RND(17) TF_RND(29) TF_RND(16) TF_RND(24)
    x0 += k1;  x1 += ks2 + 4u;
    TF_RND(13) TF_RND(15) TF_RND(26) TF_RND(6)
    x0 += ks2; x1 += k0 + 5u;
#undef TF_RND
    o0 = x0; o1 = x1;
}

__device__ __forceinline__ float bits_to_uniform(unsigned b) {
    // jax.random.uniform float32 path: bitcast((bits>>9)|0x3f800000) - 1
    return __uint_as_float((b >> 9) | 0x3f800000u) - 1.0f;
}

// ---------------------------------------------------------------------------
// K1: Vst = relu(w_pre @ eps + b_pre), plus per-block sum for mean(V)
// grid 256 x 256 threads, one column per thread
// ---------------------------------------------------------------------------
__global__ __launch_bounds__(256) void k_preconv(const float* __restrict__ eps,
                                                 const float* __restrict__ wpre,
                                                 const float* __restrict__ bpre) {
    __shared__ __align__(16) float sT[4096];   // transposed w_pre: [c][t]
    __shared__ float sb[64];
    __shared__ float ssum[256];
    int tid = threadIdx.x;
    for (int i = tid; i < 4096; i += 256) {
        int t = i >> 6, c = i & 63;
        sT[c * 64 + t] = wpre[i];
    }
    if (tid < 64) sb[tid] = bpre[tid];
    __syncthreads();

    int m = blockIdx.x * 256 + tid;
    float acc[64];
#pragma unroll
    for (int t = 0; t < 64; t++) acc[t] = sb[t];

#pragma unroll 1
    for (int c = 0; c < 64; c++) {
        float e = eps[c * MCOLS + m];
        const float4* wr = (const float4*)&sT[c * 64];
#pragma unroll
        for (int q = 0; q < 16; q++) {
            float4 w = wr[q];
            acc[4 * q + 0] += w.x * e;
            acc[4 * q + 1] += w.y * e;
            acc[4 * q + 2] += w.z * e;
            acc[4 * q + 3] += w.w * e;
        }
    }
    float ls = 0.f;
#pragma unroll
    for (int t = 0; t < 64; t++) {
        float v = fmaxf(acc[t], 0.f);
        g_V[t * MCOLS + m] = v;
        ls += v;
    }
    ssum[tid] = ls; __syncthreads();
    for (int s = 128; s; s >>= 1) { if (tid < s) ssum[tid] += ssum[tid + s]; __syncthreads(); }
    if (tid == 0) g_red[blockIdx.x] = ssum[0];
}

// ---------------------------------------------------------------------------
// K2: avg = sqrt(mean(V)/L); derive kW, kH via partitionable threefry split
//     split(key(0)): lane i -> cipher(key=(0,0), counter=(0, i)); key_i = (o0, o1)
// ---------------------------------------------------------------------------
__global__ void k_scalar1() {
    __shared__ float s[256];
    int tid = threadIdx.x;
    s[tid] = g_red[tid];
    __syncthreads();
    for (int st = 128; st; st >>= 1) { if (tid < st) s[tid] += s[tid + st]; __syncthreads(); }
    if (tid == 0) {
        float mean = s[0] / (float)(TCH * MCOLS);
        g_avg = sqrtf(mean / (float)LRANK);
        unsigned o0, o1;
        tf2x32(0u, 0u, 0u, 0u, o0, o1); g_keys[0] = o0; g_keys[1] = o1;  // kW
        tf2x32(0u, 0u, 0u, 1u, o0, o1); g_keys[2] = o0; g_keys[3] = o1;  // kH
    }
}

// ---------------------------------------------------------------------------
// K3: W0, H0 init. Partitionable random_bits: bits[i] = o0 ^ o1 of
//     cipher(key, (hi=0, lo=i)); uniform = bitcast trick; scale by avg.
//     grid 2048 x 256 = 524288 threads (H0 flat); first 512 also do W0.
// ---------------------------------------------------------------------------
__global__ void k_init() {
    unsigned i = blockIdx.x * 256u + threadIdx.x;   // < 524288
    float avg = g_avg;
    unsigned o0, o1;
    tf2x32(g_keys[2], g_keys[3], 0u, i, o0, o1);
    g_H[i] = avg * bits_to_uniform(o0 ^ o1);
    if (i < TCH * LRANK) {
        tf2x32(g_keys[0], g_keys[1], 0u, i, o0, o1);
        g_W[i] = avg * bits_to_uniform(o0 ^ o1);
    }
}

// ---------------------------------------------------------------------------
// K4: one NMF iteration, H-side + partial reductions for the W update.
//   - compute WtW in shared
//   - per column: wtv = Wt*Vcol ; Hnew = H*wtv/(WtW*H + eps)
//   - per block: partial VHt (V @ Hnew^T) and HHt (Hnew @ Hnew^T)
//   grid MUST be 128 blocks x 256 threads (512 columns per block, 2 reps)
// ---------------------------------------------------------------------------
__global__ __launch_bounds__(256) void k_iterH() {
    __shared__ __align__(16) float sW[512];
    __shared__ __align__(16) float sWtW[64];
    __shared__ float sHn[8][256];
    int tid = threadIdx.x, lane = tid & 31, warp = tid >> 5;
    int m0 = blockIdx.x * 512;

    for (int i = tid; i < 512; i += 256) sW[i] = g_W[i];
    __syncthreads();
    if (tid < 64) {
        int l = tid >> 3, j = tid & 7;
        float s = 0.f;
#pragma unroll 8
        for (int t = 0; t < 64; t++) s += sW[t * 8 + l] * sW[t * 8 + j];
        sWtW[tid] = s;
    }
    __syncthreads();

    float acc[9][8];
#pragma unroll
    for (int a = 0; a < 9; a++)
#pragma unroll
        for (int l = 0; l < 8; l++) acc[a][l] = 0.f;

#pragma unroll 1
    for (int rep = 0; rep < 2; rep++) {
        int m = m0 + rep * 256 + tid;
        float h[8], wtv[8];
#pragma unroll
        for (int l = 0; l < 8; l++) { h[l] = g_H[l * MCOLS + m]; wtv[l] = 0.f; }
#pragma unroll 4
        for (int t = 0; t < 64; t++) {
            float v = g_V[t * MCOLS + m];
            const float4* w4 = (const float4*)&sW[t * 8];
            float4 wa = w4[0], wb = w4[1];
            wtv[0] += wa.x * v; wtv[1] += wa.y * v; wtv[2] += wa.z * v; wtv[3] += wa.w * v;
            wtv[4] += wb.x * v; wtv[5] += wb.y * v; wtv[6] += wb.z * v; wtv[7] += wb.w * v;
        }
#pragma unroll
        for (int l = 0; l < 8; l++) {
            const float4* q4 = (const float4*)&sWtW[l * 8];
            float4 qa = q4[0], qb = q4[1];
            float den = EPS_F
                + qa.x * h[0] + qa.y * h[1] + qa.z * h[2] + qa.w * h[3]
                + qb.x * h[4] + qb.y * h[5] + qb.z * h[6] + qb.w * h[7];
            float hn = h[l] * wtv[l] / den;
            g_H[l * MCOLS + m] = hn;
            sHn[l][tid] = hn;
        }
        __syncthreads();

        // phase 2: warp w handles V rows [8w, 8w+8) and Hn row w
#pragma unroll 1
        for (int gg = 0; gg < 8; gg++) {
            int mm = gg * 32 + lane;
            float hl[8];
#pragma unroll
            for (int l = 0; l < 8; l++) hl[l] = sHn[l][mm];
#pragma unroll
            for (int tt = 0; tt < 8; tt++) {
                float v = g_V[(warp * 8 + tt) * MCOLS + m0 + rep * 256 + mm];
#pragma unroll
                for (int l = 0; l < 8; l++) acc[tt][l] += v * hl[l];
            }
            float hw = sHn[warp][mm];
#pragma unroll
            for (int l = 0; l < 8; l++) acc[8][l] += hw * hl[l];
        }
        __syncthreads();
    }

    // deterministic lane reduction (butterfly)
#pragma unroll
    for (int a = 0; a < 9; a++)
#pragma unroll
        for (int l = 0; l < 8; l++) {
            float x = acc[a][l];
#pragma unroll
            for (int s = 16; s; s >>= 1) x += __shfl_xor_sync(0xffffffffu, x, s);
            acc[a][l] = x;
        }
    if (lane == 0) {
        int bid = blockIdx.x;
#pragma unroll
        for (int tt = 0; tt < 8; tt++)
#pragma unroll
            for (int l = 0; l < 8; l++)
                g_partial[((warp * 8 + tt) * 8 + l) * 128 + bid] = acc[tt][l];
#pragma unroll
        for (int l = 0; l < 8; l++)
            g_partial[(512 + warp * 8 + l) * 128 + bid] = acc[8][l];
    }
}

// ---------------------------------------------------------------------------
// K5: reduce partials and update W.  1 block x 576 threads.
//   tid < 512 : VHt[t][l]   (t = tid>>3, l = tid&7)
//   tid >= 512: HHt[row][l] (row = (tid-512)>>3, l = (tid-512)&7)
//   W[t][l] *= VHt[t][l] / (sum_j W[t][j]*HHt[j][l] + eps)
// ---------------------------------------------------------------------------
__global__ __launch_bounds__(576) void k_iterW() {
    __shared__ float sVHt[512];
    __shared__ float sHHt[64];
    int tid = threadIdx.x;
    float s = 0.f;
    {
        const float4* p = (const float4*)&g_partial[tid * 128];
#pragma unroll 8
        for (int b = 0; b < 32; b++) { float4 v = p[b]; s += (v.x + v.y) + (v.z + v.w); }
    }
    if (tid < 512) sVHt[tid] = s; else sHHt[tid - 512] = s;
    __syncthreads();
    float wn = 0.f;
    if (tid < 512) {
        int t = tid >> 3, l = tid & 7;
        float den = EPS_F;
#pragma unroll
        for (int j = 0; j < 8; j++) den += g_W[t * 8 + j] * sHHt[j * 8 + l];
        wn = g_W[tid] * sVHt[tid] / den;
    }
    __syncthreads();   // all reads of old W done before any write
    if (tid < 512) g_W[tid] = wn;
}

// ---------------------------------------------------------------------------
// K6: A = w_post1 @ W  (64x8).  1 block x 512 threads.
// ---------------------------------------------------------------------------
__global__ void k_postA(const float* __restrict__ wp1) {
    int tid = threadIdx.x;
    int t = tid >> 3, l = tid & 7;
    float s = 0.f;
#pragma unroll 8
    for (int c = 0; c < 64; c++) s += wp1[t * 64 + c] * g_W[c * 8 + l];
    g_A[tid] = s;
}

// ---------------------------------------------------------------------------
// K7: per column: vhat = W@h (error), y = relu(A@h), out = w_post2 @ y
// ---------------------------------------------------------------------------
__global__ __launch_bounds__(256) void k_final(const float* __restrict__ wp2,
                                               float* __restrict__ out) {
    __shared__ __align__(16) float sW[512];
    __shared__ __align__(16) float sA[512];
    __shared__ __align__(16) float sP[4096];
    __shared__ float ssum[256];
    int tid = threadIdx.x;
    for (int i = tid; i < 512; i += 256) { sW[i] = g_W[i]; sA[i] = g_A[i]; }
    for (int i = tid; i < 4096; i += 256) sP[i] = wp2[i];
    __syncthreads();

    int m = blockIdx.x * 256 + tid;
    float h[8];
#pragma unroll
    for (int l = 0; l < 8; l++) h[l] = g_H[l * MCOLS + m];

    float y[64];
    float err = 0.f;
#pragma unroll
    for (int t = 0; t < 64; t++) {
        const float4* w4 = (const float4*)&sW[t * 8];
        float4 wa = w4[0], wb = w4[1];
        float vh = wa.x * h[0] + wa.y * h[1] + wa.z * h[2] + wa.w * h[3]
                 + wb.x * h[4] + wb.y * h[5] + wb.z * h[6] + wb.w * h[7];
        const float4* a4 = (const float4*)&sA[t * 8];
        float4 aa = a4[0], ab = a4[1];
        float ya = aa.x * h[0] + aa.y * h[1] + aa.z * h[2] + aa.w * h[3]
                 + ab.x * h[4] + ab.y * h[5] + ab.z * h[6] + ab.w * h[7];
        float d = g_V[t * MCOLS + m] - vh;
        err += d * d;
        y[t] = fmaxf(ya, 0.f);
    }

#pragma unroll 1
    for (int t = 0; t < 64; t++) {
        const float4* p4 = (const float4*)&sP[t * 64];
        float o = 0.f;
#pragma unroll
        for (int q = 0; q < 16; q++) {
            float4 w = p4[q];
            o += w.x * y[4 * q] + w.y * y[4 * q + 1] + w.z * y[4 * q + 2] + w.w * y[4 * q + 3];
        }
        out[t * MCOLS + m] = o;
    }

    ssum[tid] = err; __syncthreads();
    for (int s = 128; s; s >>= 1) { if (tid < s) ssum[tid] += ssum[tid + s]; __syncthreads(); }
    if (tid == 0) g_red2[blockIdx.x] = ssum[0];
}

// ---------------------------------------------------------------------------
// K8: error = sqrt(sum of squared diffs); stored at out[out_size-1]
// ---------------------------------------------------------------------------
__global__ void k_err(float* __restrict__ out, int out_size) {
    __shared__ float s[256];
    int tid = threadIdx.x;
    s[tid] = g_red2[tid];
    __syncthreads();
    for (int st = 128; st; st >>= 1) { if (tid < st) s[tid] += s[tid + st]; __syncthreads(); }
    if (tid == 0) out[out_size - 1] = sqrtf(s[0]);
}

// ---------------------------------------------------------------------------
extern "C" void kernel_launch(void* const* d_in, const int* in_sizes, int n_in,
                              void* d_out, int out_size) {
    const float* eps  = (const float*)d_in[0];
    const float* wpre = (const float*)d_in[1];
    const float* bpre = (const float*)d_in[2];
    const float* wp1  = (const float*)d_in[3];
    const float* wp2  = (const float*)d_in[4];
    float* out = (float*)d_out;

    k_preconv<<<256, 256>>>(eps, wpre, bpre);
    k_scalar1<<<1, 256>>>();
    k_init<<<2048, 256>>>();
    for (int it = 0; it < NMF_ITERS; it++) {
        k_iterH<<<128, 256>>>();
        k_iterW<<<1, 576>>>();
    }
    k_postA<<<1, 512>>>(wp1);
    k_final<<<256, 256>>>(wp2, out);
    k_err<<<1, 256>>>(out, out_size);
}